// round 9
// baseline (speedup 1.0000x reference)
#include <cuda_runtime.h>
#include <cuda_fp16.h>
#include <cstdint>
#include <cstdio>

// Problem constants
#define Bv   32
#define Cv   64
#define Tv   12
#define Nv   1024
#define KSv  3
#define OUTv 64

#define Kdim   (KSv*Nv)        // 3072
#define Mrows  (Bv*Cv*Tv)      // 24576
#define BT     (Bv*Tv)         // 384

// ---------------- scratch ----------------
__device__ __half g_LkH[KSv * Nv * Nv];            // 6.3 MB   fp16(Lk), natural [k][n][m]
__device__ __half g_YH [(size_t)Mrows * Kdim];     // 151 MB   channel-mix output (fp16)
__device__ __half g_xH [(size_t)Mrows * Nv];       // 50 MB    fp16(x)
__device__ __half g_X1 [(size_t)Mrows * Nv];       // 50 MB    layer-1 output (fp16)
__device__ __half g_X2 [(size_t)Mrows * Nv];       // 50 MB    layer-2 output (fp16)
__device__ __half g_Th1[192 * 64];                 // 24 KB    theta1 transposed [p][i] fp16
__device__ __half g_Th2[192 * 64];                 // 24 KB    theta2 transposed [p][i] fp16

static __half *pLkH = nullptr, *pYH = nullptr, *pxH = nullptr;
static __half *pX1 = nullptr, *pX2 = nullptr, *pTh1 = nullptr, *pTh2 = nullptr;

// ---- helpers ----
__device__ __forceinline__ void mma_f16(float& c0, float& c1, float& c2, float& c3,
                                        uint32_t a0, uint32_t a1, uint32_t a2, uint32_t a3,
                                        uint32_t b0, uint32_t b1) {
    asm volatile(
        "mma.sync.aligned.m16n8k16.row.col.f32.f16.f16.f32 "
        "{%0,%1,%2,%3}, {%4,%5,%6,%7}, {%8,%9}, {%0,%1,%2,%3};"
        : "+f"(c0), "+f"(c1), "+f"(c2), "+f"(c3)
        : "r"(a0), "r"(a1), "r"(a2), "r"(a3), "r"(b0), "r"(b1));
}

__device__ __forceinline__ void ldsm_x4(uint32_t& r0, uint32_t& r1, uint32_t& r2, uint32_t& r3,
                                        uint32_t addr) {
    asm volatile("ldmatrix.sync.aligned.m8n8.x4.shared.b16 {%0,%1,%2,%3}, [%4];"
                 : "=r"(r0), "=r"(r1), "=r"(r2), "=r"(r3) : "r"(addr));
}
__device__ __forceinline__ void ldsm_x4_t(uint32_t& r0, uint32_t& r1, uint32_t& r2, uint32_t& r3,
                                          uint32_t addr) {
    asm volatile("ldmatrix.sync.aligned.m8n8.x4.trans.shared.b16 {%0,%1,%2,%3}, [%4];"
                 : "=r"(r0), "=r"(r1), "=r"(r2), "=r"(r3) : "r"(addr));
}

__device__ __forceinline__ void cp16(uint32_t dst_smem, const void* src) {
    asm volatile("cp.async.cg.shared.global [%0], [%1], 16;" :: "r"(dst_smem), "l"(src));
}
__device__ __forceinline__ void cp_commit() { asm volatile("cp.async.commit_group;"); }

// ---------------- prep kernels ----------------
__global__ __launch_bounds__(256) void prep_fp16(const float* __restrict__ src,
                                                 __half* __restrict__ dst)
{
    size_t i = (size_t)blockIdx.x * 1024 + threadIdx.x * 4;
    float4 v = *reinterpret_cast<const float4*>(src + i);
    *reinterpret_cast<__half2*>(dst + i)     = __floats2half2_rn(v.x, v.y);
    *reinterpret_cast<__half2*>(dst + i + 2) = __floats2half2_rn(v.z, v.w);
}

// theta [i][p] (64 x 192) fp32 -> thT [p][i] fp16
__global__ __launch_bounds__(256) void prep_theta(const float* __restrict__ theta,
                                                  __half* __restrict__ thT)
{
    for (int idx = threadIdx.x; idx < 192 * 64; idx += 256) {
        int i = idx / 192;
        int p = idx - i * 192;
        thT[p * 64 + i] = __float2half_rn(theta[idx]);
    }
}

// ---------------- kernel B: channel mix, full fp16 + cp.async ----------------
// Y[p=(o,k)][m] = sum_i thT[p][i] * X[i][m]  per (b,t), m-block of 128.
#define CM_AROW 144           // bytes per A row (64 halfs + 8 pad)
#define CM_BROW 272           // bytes per B row (128 halfs + 8 pad)

__global__ __launch_bounds__(256, 2) void channel_mix_f16(const __half* __restrict__ X,
                                                          const __half* __restrict__ thT,
                                                          __half* __restrict__ Y)
{
    __shared__ __half As[192 * (CM_AROW/2)];
    __shared__ __half Bs[64  * (CM_BROW/2)];
    const uint32_t smA = (uint32_t)__cvta_generic_to_shared(As);
    const uint32_t smB = (uint32_t)__cvta_generic_to_shared(Bs);

    const int bt = blockIdx.x;
    const int b  = bt / Tv;
    const int t  = bt % Tv;
    const int m0 = blockIdx.y * 128;
    const int tid  = threadIdx.x;
    const int wid  = tid >> 5;
    const int lane = tid & 31;
    const int gq = lane >> 2;
    const int tg = lane & 3;
    const int wm = (wid & 3) * 48;
    const int wn = (wid >> 2) * 64;

    // theta: 192 rows x 128B data -> 1536 cp16 (6/thread)
    #pragma unroll
    for (int l = 0; l < 6; l++) {
        int slot = tid + 256 * l;          // 0..1535
        int p = slot >> 3, q = slot & 7;
        cp16(smA + (uint32_t)(p * CM_AROW + q * 16), thT + p * 64 + q * 8);
    }
    // X tile: 64 rows x 256B data -> 1024 cp16 (4/thread)
    #pragma unroll
    for (int l = 0; l < 4; l++) {
        int slot = tid + 256 * l;          // 0..1023
        int i = slot >> 4, q = slot & 15;
        cp16(smB + (uint32_t)(i * CM_BROW + q * 16),
             X + ((size_t)(b * Cv + i) * Tv + t) * Nv + m0 + q * 8);
    }
    cp_commit();
    asm volatile("cp.async.wait_group 0;" ::: "memory");
    __syncthreads();

    float acc[3][8][4];
    #pragma unroll
    for (int a = 0; a < 3; a++)
        #pragma unroll
        for (int c = 0; c < 8; c++)
            #pragma unroll
            for (int q = 0; q < 4; q++) acc[a][c][q] = 0.f;

    const int rowA = (lane & 7) + ((lane >> 3) & 1) * 8;   // A: non-trans
    const int colA = (lane >> 4) * 16;
    const int rowB = (lane & 7) + ((lane >> 3) & 1) * 8;   // B: trans (rows = k)
    const int colB = ((lane >> 4) & 1) * 16;

    #pragma unroll
    for (int ks = 0; ks < 4; ks++) {           // K = 64 = 4 x k16
        uint32_t af[3][4];
        #pragma unroll
        for (int mt = 0; mt < 3; mt++)
            ldsm_x4(af[mt][0], af[mt][1], af[mt][2], af[mt][3],
                    smA + (uint32_t)((wm + 16*mt + rowA) * CM_AROW + ks * 32 + colA));
        uint32_t bf[8][2];
        #pragma unroll
        for (int ntp = 0; ntp < 4; ntp++)
            ldsm_x4_t(bf[2*ntp][0], bf[2*ntp][1], bf[2*ntp+1][0], bf[2*ntp+1][1],
                      smB + (uint32_t)((ks*16 + rowB) * CM_BROW + (wn + 16*ntp) * 2 + colB));
        #pragma unroll
        for (int mt = 0; mt < 3; mt++)
            #pragma unroll
            for (int nt = 0; nt < 8; nt++)
                mma_f16(acc[mt][nt][0], acc[mt][nt][1], acc[mt][nt][2], acc[mt][nt][3],
                        af[mt][0], af[mt][1], af[mt][2], af[mt][3],
                        bf[nt][0], bf[nt][1]);
    }

    // epilogue: scatter to Y rows by (o,k) decode
    #pragma unroll
    for (int mt = 0; mt < 3; mt++) {
        int p1 = wm + 16 * mt + gq;
        int p2 = p1 + 8;
        int o1 = p1 / 3, k1 = p1 - o1 * 3;
        int o2 = p2 / 3, k2 = p2 - o2 * 3;
        size_t r1 = ((size_t)(b * Cv + o1) * Tv + t) * (size_t)Kdim + (size_t)k1 * Nv;
        size_t r2 = ((size_t)(b * Cv + o2) * Tv + t) * (size_t)Kdim + (size_t)k2 * Nv;
        #pragma unroll
        for (int nt = 0; nt < 8; nt++) {
            int c = m0 + wn + 8 * nt + 2 * tg;
            *reinterpret_cast<__half2*>(Y + r1 + c) = __floats2half2_rn(acc[mt][nt][0], acc[mt][nt][1]);
            *reinterpret_cast<__half2*>(Y + r2 + c) = __floats2half2_rn(acc[mt][nt][2], acc[mt][nt][3]);
        }
    }
}

// ---------------- kernel C: fp16 mma GEMM, single-sync pipeline + ldmatrix --
// C[r][n] = relu_h( sum_q Y[r][q]*B[n][q] + bias[o(r)] + resid[r][n] )
#define GBK 32
#define AROW 80                     // bytes per smem row (32 halfs + 8 pad)
#define STAGE_A (128*AROW)          // 10240 B
#define STAGE_BYTES (2*STAGE_A)     // 20480 B
#define NSTAGE 4
#define GSMEM_BYTES (NSTAGE*STAGE_BYTES)   // 81920 B

__global__ __launch_bounds__(256, 2) void gemm_f16(const __half* __restrict__ A,     // [Mrows,3072]
                                                   const __half* __restrict__ Bk,    // LkH [3][1024][1024]
                                                   const float*  __restrict__ bias,  // [64]
                                                   const __half* __restrict__ resid, // [Mrows,Nv] fp16
                                                   __half*       __restrict__ Cout)  // [Mrows,Nv] fp16
{
    extern __shared__ char smem[];
    const uint32_t sbase = (uint32_t)__cvta_generic_to_shared(smem);

    const int bn  = blockIdx.x;     // 0..7
    const int bm  = blockIdx.y;     // 0..191
    const int tid = threadIdx.x;
    const int wid = tid >> 5;
    const int lane = tid & 31;
    const int gq  = lane >> 2;
    const int tg  = lane & 3;
    const int wm  = (wid & 3) * 32;
    const int wn  = (wid >> 2) * 64;

    const __half* Abase = A + (size_t)bm * 128 * Kdim;
    const __half* Bbase = Bk + (size_t)bn * 128 * Nv;

    auto fill_stage = [&](int s, int c) {
        const int k  = c >> 5;
        const int m0 = (c & 31) << 5;
        const __half* Asrc = Abase + (size_t)c * GBK;
        const __half* Bsrc = Bbase + ((size_t)k << 20) + m0;
        const uint32_t Asm = sbase + s * STAGE_BYTES;
        const uint32_t Bsm = Asm + STAGE_A;
        #pragma unroll
        for (int l = 0; l < 2; l++) {
            int slot = tid * 2 + l;            // 0..511
            int row = slot >> 2, q4 = slot & 3;
            cp16(Asm + row * AROW + q4 * 16, Asrc + (size_t)row * Kdim + q4 * 8);
        }
        #pragma unroll
        for (int l = 0; l < 2; l++) {
            int slot = tid * 2 + l;
            int row = slot >> 2, q4 = slot & 3;
            cp16(Bsm + row * AROW + q4 * 16, Bsrc + (size_t)row * Nv + q4 * 8);
        }
        cp_commit();
    };

    float acc[2][8][4];
    #pragma unroll
    for (int i = 0; i < 2; i++)
        #pragma unroll
        for (int j = 0; j < 8; j++)
            #pragma unroll
            for (int q = 0; q < 4; q++) acc[i][j][q] = 0.f;

    fill_stage(0, 0);
    fill_stage(1, 1);
    fill_stage(2, 2);

    const int rowA = (lane & 7) + ((lane >> 3) & 1) * 8;
    const int colA = (lane >> 4) * 16;
    const int rowB = (lane & 7) + ((lane >> 4) & 1) * 8;
    const int colB = ((lane >> 3) & 1) * 16;

    const int NITER = Kdim / GBK;          // 96
    for (int it = 0; it < NITER; it++) {
        asm volatile("cp.async.wait_group %0;" :: "n"(NSTAGE - 2) : "memory");
        __syncthreads();

        if (it + NSTAGE - 1 < NITER) fill_stage((it + NSTAGE - 1) & 3, it + NSTAGE - 1);
        else                         cp_commit();

        const uint32_t Acur = sbase + (it & 3) * STAGE_BYTES;
        const uint32_t Bcur = Acur + STAGE_A;

        #pragma unroll
        for (int kh = 0; kh < 2; kh++) {
            const int kb = kh * 32;
            uint32_t af[2][4];
            #pragma unroll
            for (int mt = 0; mt < 2; mt++)
                ldsm_x4(af[mt][0], af[mt][1], af[mt][2], af[mt][3],
                        Acur + (uint32_t)((wm + 16*mt + rowA) * AROW + kb + colA));
            uint32_t bf[8][2];
            #pragma unroll
            for (int ntp = 0; ntp < 4; ntp++)
                ldsm_x4(bf[2*ntp][0], bf[2*ntp][1], bf[2*ntp+1][0], bf[2*ntp+1][1],
                        Bcur + (uint32_t)((wn + 16*ntp + rowB) * AROW + kb + colB));
            #pragma unroll
            for (int mt = 0; mt < 2; mt++)
                #pragma unroll
                for (int nt = 0; nt < 8; nt++)
                    mma_f16(acc[mt][nt][0], acc[mt][nt][1], acc[mt][nt][2], acc[mt][nt][3],
                            af[mt][0], af[mt][1], af[mt][2], af[mt][3],
                            bf[nt][0], bf[nt][1]);
        }
    }

    // epilogue: bias + fp16 residual + relu, fp16 out
    #pragma unroll
    for (int mt = 0; mt < 2; mt++) {
        int r1 = bm * 128 + wm + 16 * mt + gq;
        int r2 = r1 + 8;
        int o1 = (r1 / Tv) & (Cv - 1);
        int o2 = (r2 / Tv) & (Cv - 1);
        float bv1 = bias[o1];
        float bv2 = bias[o2];
        #pragma unroll
        for (int nt = 0; nt < 8; nt++) {
            int c = bn * 128 + wn + 8 * nt + 2 * tg;
            __half2 res1 = *reinterpret_cast<const __half2*>(resid + (size_t)r1 * Nv + c);
            __half2 res2 = *reinterpret_cast<const __half2*>(resid + (size_t)r2 * Nv + c);
            float v0 = fmaxf(acc[mt][nt][0] + bv1 + __low2float(res1),  0.f);
            float v1 = fmaxf(acc[mt][nt][1] + bv1 + __high2float(res1), 0.f);
            float v2 = fmaxf(acc[mt][nt][2] + bv2 + __low2float(res2),  0.f);
            float v3 = fmaxf(acc[mt][nt][3] + bv2 + __high2float(res2), 0.f);
            *reinterpret_cast<__half2*>(Cout + (size_t)r1 * Nv + c) = __floats2half2_rn(v0, v1);
            *reinterpret_cast<__half2*>(Cout + (size_t)r2 * Nv + c) = __floats2half2_rn(v2, v3);
        }
    }
}

// ---------------- kernel D: final FC (fp16 input, fp32 out) ----------------
__global__ __launch_bounds__(256) void fc_kernel(const __half* __restrict__ X2c,
                                                 const float* __restrict__ fcw,
                                                 const float* __restrict__ fcb,
                                                 float*       __restrict__ out)
{
    __shared__ float xs[Cv][65];
    __shared__ float ws[Cv][OUTv];
    __shared__ float bs[OUTv];

    int bt = blockIdx.x;
    int b  = bt / Tv;
    int t  = bt % Tv;
    int n0 = blockIdx.y * 64;
    int tid = threadIdx.x;

    for (int idx = tid; idx < Cv * OUTv; idx += 256) {
        int j = idx >> 6;
        int o = idx & 63;
        ws[o][j] = fcw[idx];
    }
    if (tid < OUTv) bs[tid] = fcb[tid];
    for (int idx = tid; idx < Cv * 64; idx += 256) {
        int o  = idx >> 6;
        int nl = idx & 63;
        xs[o][nl] = __half2float(X2c[((size_t)(b * Cv + o) * Tv + t) * Nv + n0 + nl]);
    }
    __syncthreads();

    int nl = tid & 63;
    int jg = tid >> 6;
    float acc[16];
    #pragma unroll
    for (int jj = 0; jj < 16; jj++) acc[jj] = 0.f;

    for (int o = 0; o < Cv; o++) {
        float xv = xs[o][nl];
        const float4* wrow = reinterpret_cast<const float4*>(&ws[o][jg * 16]);
        #pragma unroll
        for (int q = 0; q < 4; q++) {
            float4 w = wrow[q];
            acc[q * 4 + 0] += w.x * xv;
            acc[q * 4 + 1] += w.y * xv;
            acc[q * 4 + 2] += w.z * xv;
            acc[q * 4 + 3] += w.w * xv;
        }
    }

    size_t base = (((size_t)bt) * Nv + n0 + nl) * OUTv + jg * 16;
    #pragma unroll
    for (int q = 0; q < 4; q++) {
        float4 v;
        v.x = acc[q * 4 + 0] + bs[jg * 16 + q * 4 + 0];
        v.y = acc[q * 4 + 1] + bs[jg * 16 + q * 4 + 1];
        v.z = acc[q * 4 + 2] + bs[jg * 16 + q * 4 + 2];
        v.w = acc[q * 4 + 3] + bs[jg * 16 + q * 4 + 3];
        *reinterpret_cast<float4*>(out + base + q * 4) = v;
    }
}

// ---------------- static-init module materialization ----------------
namespace {
struct ModuleLoader {
    ModuleLoader() {
        cudaFree(0);
        cudaGetSymbolAddress((void**)&pLkH, g_LkH);
        cudaGetSymbolAddress((void**)&pYH,  g_YH);
        cudaGetSymbolAddress((void**)&pxH,  g_xH);
        cudaGetSymbolAddress((void**)&pX1,  g_X1);
        cudaGetSymbolAddress((void**)&pX2,  g_X2);
        cudaGetSymbolAddress((void**)&pTh1, g_Th1);
        cudaGetSymbolAddress((void**)&pTh2, g_Th2);
        cudaMemset(pLkH, 0, 4);
        cudaMemset(pYH,  0, 4);
        cudaMemset(pxH,  0, 4);
        cudaMemset(pX1,  0, 4);
        cudaMemset(pX2,  0, 4);
        cudaMemset(pTh1, 0, 4);
        cudaMemset(pTh2, 0, 4);
        cudaFuncSetAttribute(gemm_f16, cudaFuncAttributeMaxDynamicSharedMemorySize, GSMEM_BYTES);
        cudaDeviceSynchronize();
    }
};
ModuleLoader g_loader;
}

// ---------------- launch ----------------
extern "C" void kernel_launch(void* const* d_in, const int* in_sizes, int n_in,
                              void* d_out, int out_size)
{
    const float* x      = (const float*)d_in[0];
    const float* Lk     = (const float*)d_in[1];
    const float* theta1 = (const float*)d_in[2];
    const float* b1     = (const float*)d_in[3];
    const float* theta2 = (const float*)d_in[4];
    const float* b2     = (const float*)d_in[5];
    const float* fc_w   = (const float*)d_in[6];
    const float* fc_b   = (const float*)d_in[7];
    float* out = (float*)d_out;

    // 1) prep: fp16 conversions + theta transpose
    prep_fp16<<<KSv * Nv * Nv / 1024, 256>>>(Lk, pLkH);
    prep_fp16<<<(int)((size_t)Mrows * Nv / 1024), 256>>>(x, pxH);
    prep_theta<<<1, 256>>>(theta1, pTh1);
    prep_theta<<<1, 256>>>(theta2, pTh2);

    // 2) layer 1
    channel_mix_f16<<<dim3(BT, Nv / 128), 256>>>(pxH, pTh1, pYH);
    gemm_f16<<<dim3(Nv / 128, Mrows / 128), 256, GSMEM_BYTES>>>(pYH, pLkH, b1, pxH, pX1);

    // 3) layer 2
    channel_mix_f16<<<dim3(BT, Nv / 128), 256>>>(pX1, pTh2, pYH);
    gemm_f16<<<dim3(Nv / 128, Mrows / 128), 256, GSMEM_BYTES>>>(pYH, pLkH, b2, pX1, pX2);

    // 4) final FC
    fc_kernel<<<dim3(BT, Nv / 64), 256>>>(pX2, fc_w, fc_b, out);
}